// round 4
// baseline (speedup 1.0000x reference)
#include <cuda_runtime.h>
#include <cuda_bf16.h>
#include <stdint.h>
#include <math.h>

#define N_NODES 8192
#define IN_F    512
#define OUT_F   256

__device__ float g_support[N_NODES * OUT_F];

#define BM 64
#define BN 128
#define BK 64
#define PITCH_B 144                     // 72 bf16 per row: 16B-step swizzle-free ldmatrix
#define A_TILE  (BM * PITCH_B)          // 9216
#define B_TILE  (BN * PITCH_B)          // 18432
#define STAGE   (2 * A_TILE + 2 * B_TILE) // 55296 (Ahi, Alo, Bhi, Blo)
#define SMEM_BYTES (2 * STAGE)          // 110592

__device__ __forceinline__ uint32_t smem_u32(const void* p) {
    uint32_t a;
    asm("{ .reg .u64 t; cvta.to.shared.u64 t, %1; cvt.u32.u64 %0, t; }" : "=r"(a) : "l"(p));
    return a;
}

__device__ __forceinline__ void ldsm_x4(uint32_t r[4], uint32_t addr) {
    asm volatile("ldmatrix.sync.aligned.m8n8.x4.shared.b16 {%0,%1,%2,%3}, [%4];"
                 : "=r"(r[0]), "=r"(r[1]), "=r"(r[2]), "=r"(r[3]) : "r"(addr));
}

__device__ __forceinline__ void mma16816(float c[4],
                                         uint32_t a0, uint32_t a1, uint32_t a2, uint32_t a3,
                                         uint32_t b0, uint32_t b1) {
    asm volatile(
        "mma.sync.aligned.m16n8k16.row.col.f32.bf16.bf16.f32 "
        "{%0,%1,%2,%3}, {%4,%5,%6,%7}, {%8,%9}, {%0,%1,%2,%3};"
        : "+f"(c[0]), "+f"(c[1]), "+f"(c[2]), "+f"(c[3])
        : "r"(a0), "r"(a1), "r"(a2), "r"(a3), "r"(b0), "r"(b1));
}

__device__ __forceinline__ void split2(float x, float y, uint32_t& hi, uint32_t& lo) {
    __nv_bfloat162 h = __floats2bfloat162_rn(x, y);
    float2 hf = __bfloat1622float2(h);
    __nv_bfloat162 l = __floats2bfloat162_rn(x - hf.x, y - hf.y);
    hi = *reinterpret_cast<uint32_t*>(&h);
    lo = *reinterpret_cast<uint32_t*>(&l);
}

// C[64,128] tile = op(A)[64,K] @ B[K,128] via 2-term bf16 split (3 mmas).
// smem: A [m][k] k-contig, B [n][k] k-contig (transposed on store), pitch 144B.
template <bool SQ, bool EPI>
__global__ __launch_bounds__(256, 2)
void mma_gemm(const float* __restrict__ A, const float* __restrict__ B,
              const float* __restrict__ bias, float* __restrict__ C,
              int K, int lda, int ldb, int ldc)
{
    extern __shared__ __align__(1024) char smem[];
    const uint32_t sbase = smem_u32(smem);
    const int tid = threadIdx.x;
    const int bm = blockIdx.y * BM;
    const int bn = blockIdx.x * BN;
    const int wid = tid >> 5, lid = tid & 31;
    const int wm = (wid & 1) * 32;       // 2 warps in M
    const int wn = (wid >> 1) * 32;      // 4 warps in N
    const int grp = lid >> 2, quad = lid & 3;

    // global-load mappings
    const int a_row = tid >> 2, a_k4 = tid & 3;   // A: 4 float4/thread
    const int b_n = tid & 127, b_kq = tid >> 7;   // B: 8 kq-chunks/thread (4 scalars each)

    float acc[2][4][4];
    #pragma unroll
    for (int i = 0; i < 2; i++)
        #pragma unroll
        for (int j = 0; j < 4; j++)
            #pragma unroll
            for (int e = 0; e < 4; e++) acc[i][j][e] = 0.0f;

    const float* Abase = A + (size_t)(bm + a_row) * lda;
    const float* Bbase = B + bn + b_n;
    const int nkt = K / BK;

    float4 aReg[4];
    float  bReg[4][4];

    // ---- staging helpers ----
    auto LDG_A = [&](int t) {
        #pragma unroll
        for (int j = 0; j < 4; j++)
            aReg[j] = *reinterpret_cast<const float4*>(Abase + t * BK + (a_k4 + 4 * j) * 4);
    };
    auto LDG_B = [&](int t, int half) {
        #pragma unroll
        for (int j = 0; j < 4; j++) {
            const int kq = b_kq + 2 * (j + 4 * half);
            #pragma unroll
            for (int i = 0; i < 4; i++)
                bReg[j][i] = Bbase[(size_t)(t * BK + kq * 4 + i) * ldb];
        }
    };
    auto STS_A = [&](int s) {
        char* st = smem + s * STAGE;
        #pragma unroll
        for (int j = 0; j < 4; j++) {
            float4 v = aReg[j];
            if (SQ) { v.x *= v.x; v.y *= v.y; v.z *= v.z; v.w *= v.w; }
            uint32_t h0, l0, h1, l1;
            split2(v.x, v.y, h0, l0);
            split2(v.z, v.w, h1, l1);
            const int off = a_row * PITCH_B + (a_k4 + 4 * j) * 8;
            *reinterpret_cast<uint2*>(st + off)          = make_uint2(h0, h1);
            *reinterpret_cast<uint2*>(st + A_TILE + off) = make_uint2(l0, l1);
        }
    };
    auto STS_B = [&](int s, int half) {
        char* st = smem + s * STAGE + 2 * A_TILE;
        #pragma unroll
        for (int j = 0; j < 4; j++) {
            const int kq = b_kq + 2 * (j + 4 * half);
            uint32_t h0, l0, h1, l1;
            split2(bReg[j][0], bReg[j][1], h0, l0);
            split2(bReg[j][2], bReg[j][3], h1, l1);
            const int off = b_n * PITCH_B + kq * 8;
            *reinterpret_cast<uint2*>(st + off)          = make_uint2(h0, h1);
            *reinterpret_cast<uint2*>(st + B_TILE + off) = make_uint2(l0, l1);
        }
    };

    // fragment lane addressing (constant across k-tiles)
    const uint32_t a_lane_off = (uint32_t)((wm + (lid & 15)) * PITCH_B + (lid >> 4) * 16);
    const uint32_t b_lane_off = (uint32_t)(2 * A_TILE +
                                (wn + (lid & 7) + ((lid >> 4) << 3)) * PITCH_B +
                                ((lid >> 3) & 1) * 16);

    auto MMA_KK = [&](uint32_t stg, int kk) {
        uint32_t ah[2][4], al[2][4], bh[2][4], bl[2][4];
        #pragma unroll
        for (int mt = 0; mt < 2; mt++) {
            const uint32_t ad = stg + a_lane_off + mt * (16 * PITCH_B) + kk * 32;
            ldsm_x4(ah[mt], ad);
            ldsm_x4(al[mt], ad + A_TILE);
        }
        #pragma unroll
        for (int np = 0; np < 2; np++) {
            const uint32_t bd = stg + b_lane_off + np * (16 * PITCH_B) + kk * 32;
            ldsm_x4(bh[np], bd);
            ldsm_x4(bl[np], bd + B_TILE);
        }
        #pragma unroll
        for (int mt = 0; mt < 2; mt++)
            #pragma unroll
            for (int nt = 0; nt < 4; nt++) {
                const uint32_t b0h = bh[nt >> 1][(nt & 1) * 2];
                const uint32_t b1h = bh[nt >> 1][(nt & 1) * 2 + 1];
                const uint32_t b0l = bl[nt >> 1][(nt & 1) * 2];
                const uint32_t b1l = bl[nt >> 1][(nt & 1) * 2 + 1];
                mma16816(acc[mt][nt], ah[mt][0], ah[mt][1], ah[mt][2], ah[mt][3], b0h, b1h);
                mma16816(acc[mt][nt], ah[mt][0], ah[mt][1], ah[mt][2], ah[mt][3], b0l, b1l);
                mma16816(acc[mt][nt], al[mt][0], al[mt][1], al[mt][2], al[mt][3], b0h, b1h);
            }
    };

    // ---- prologue ----
    LDG_A(0); STS_A(0);
    LDG_B(0, 0); STS_B(0, 0);
    LDG_B(0, 1); STS_B(0, 1);
    __syncthreads();

    // ---- main loop ----
    for (int t = 0; t < nkt; t++) {
        const int s = t & 1;
        const uint32_t stg = sbase + s * STAGE;
        const bool nx = (t + 1 < nkt);

        if (nx) { LDG_A(t + 1); LDG_B(t + 1, 0); }
        MMA_KK(stg, 0);
        MMA_KK(stg, 1);
        if (nx) { STS_A(s ^ 1); STS_B(s ^ 1, 0); LDG_B(t + 1, 1); }
        MMA_KK(stg, 2);
        MMA_KK(stg, 3);
        if (nx) STS_B(s ^ 1, 1);
        __syncthreads();
    }

    // ---- epilogue ----
    #pragma unroll
    for (int nt = 0; nt < 4; nt++) {
        const int col = bn + wn + nt * 8 + 2 * quad;
        float bb0 = 0.0f, bb1 = 0.0f;
        if (EPI) { bb0 = bias[col]; bb1 = bias[col + 1]; }
        #pragma unroll
        for (int mt = 0; mt < 2; mt++) {
            const int row = bm + wm + mt * 16 + grp;
            float2 v01 = make_float2(acc[mt][nt][0], acc[mt][nt][1]);
            float2 v23 = make_float2(acc[mt][nt][2], acc[mt][nt][3]);
            if (EPI) {
                v01.x += bb0; v01.y += bb1;
                v23.x += bb0; v23.y += bb1;
                v01.x = v01.x > 0.0f ? v01.x : expm1f(v01.x);
                v01.y = v01.y > 0.0f ? v01.y : expm1f(v01.y);
                v23.x = v23.x > 0.0f ? v23.x : expm1f(v23.x);
                v23.y = v23.y > 0.0f ? v23.y : expm1f(v23.y);
            }
            *reinterpret_cast<float2*>(C + (size_t)row * ldc + col) = v01;
            *reinterpret_cast<float2*>(C + (size_t)(row + 8) * ldc + col) = v23;
        }
    }
}

extern "C" void kernel_launch(void* const* d_in, const int* in_sizes, int n_in,
                              void* d_out, int out_size)
{
    const float* input  = (const float*)d_in[0];  // [8192, 512]
    const float* adj    = (const float*)d_in[1];  // [8192, 8192]
    const float* weight = (const float*)d_in[2];  // [512, 256]
    const float* bias   = (const float*)d_in[3];  // [256]
    float* out = (float*)d_out;                   // [8192, 256]

    float* support = nullptr;
    cudaGetSymbolAddress((void**)&support, g_support);

    cudaFuncSetAttribute(mma_gemm<false, false>,
                         cudaFuncAttributeMaxDynamicSharedMemorySize, SMEM_BYTES);
    cudaFuncSetAttribute(mma_gemm<true, true>,
                         cudaFuncAttributeMaxDynamicSharedMemorySize, SMEM_BYTES);

    dim3 grid(OUT_F / BN, N_NODES / BM);  // (2, 128) = 256 CTAs

    // GEMM 1: support = input @ weight   (8192 x 512 x 256)
    mma_gemm<false, false><<<grid, 256, SMEM_BYTES>>>(
        input, weight, nullptr, support, IN_F, IN_F, OUT_F, OUT_F);

    // GEMM 2: out = ELU( (adj**2) @ support + bias )   (8192 x 8192 x 256)
    mma_gemm<true, true><<<grid, 256, SMEM_BYTES>>>(
        adj, support, bias, out, N_NODES, N_NODES, OUT_F, OUT_F);
}